// round 10
// baseline (speedup 1.0000x reference)
#include <cuda_runtime.h>
#include <cuda_fp16.h>
#include <mma.h>
#include <cstddef>
#include <cstdint>

using namespace nvcuda;

// Problem constants
#define BB    8
#define NN    2048
#define FIN   256
#define FOUT  128
#define ALPHA 0.2f

#define ROWS_TOTAL (BB * NN)          // 16384
#define NT    128                     // n-tile width
#define TILES (NN / NT)               // 16
#define CHUNKS ((size_t)ROWS_TOTAL * TILES)   // 262144
#define MAXNB 31

// Scratch (allocation-free rule: __device__ globals)
__device__ __half g_WhT[(size_t)BB * FOUT * NN];   // 4 MB, [b][o][n] (transposed)
__device__ float  g_s1[ROWS_TOTAL];
__device__ float  g_s2[ROWS_TOTAL];
// per (row, 128-tile) record: bytes [0..31) local neighbor idx, byte 31 = count
__device__ unsigned char g_rec[CHUNKS * 32];       // 8 MB

// ---------------------------------------------------------------------------
// cp.async helpers
// ---------------------------------------------------------------------------
__device__ __forceinline__ void cpa16(uint32_t dst, const void* src) {
    asm volatile("cp.async.cg.shared.global [%0], [%1], 16;" :: "r"(dst), "l"(src));
}
#define CP_COMMIT() asm volatile("cp.async.commit_group;")
#define CP_WAIT1()  asm volatile("cp.async.wait_group 1;")
#define CP_WAIT0()  asm volatile("cp.async.wait_group 0;")

// ---------------------------------------------------------------------------
// Kernel 0: compress A (134 MB, ~5% nonzero) into per-(row,128-tile) records.
// One warp per chunk: 1 LDG.128 per lane, nibble mask + warp scan compaction.
// ---------------------------------------------------------------------------
__global__ void __launch_bounds__(256) gat_compress_kernel(const float* __restrict__ A)
{
    const int lane = threadIdx.x & 31;
    const unsigned wg = (blockIdx.x * blockDim.x + threadIdx.x) >> 5;
    const unsigned nw = (gridDim.x * blockDim.x) >> 5;

    for (size_t c = wg; c < CHUNKS; c += nw) {
        float4 v = reinterpret_cast<const float4*>(A)[c * 32 + lane];
        unsigned nib = (v.x != 0.f ? 1u : 0u) | (v.y != 0.f ? 2u : 0u)
                     | (v.z != 0.f ? 4u : 0u) | (v.w != 0.f ? 8u : 0u);
        unsigned cnt = __popc(nib);
        unsigned incl = cnt;
        #pragma unroll
        for (int d = 1; d < 32; d <<= 1) {
            unsigned t = __shfl_up_sync(0xffffffffu, incl, d);
            if (lane >= d) incl += t;
        }
        unsigned p = incl - cnt;                  // exclusive prefix
        unsigned char* outp = g_rec + c * 32;
        unsigned e0 = (unsigned)lane * 4u;
        if (nib & 1u) { if (p < MAXNB) outp[p] = (unsigned char)e0;       p++; }
        if (nib & 2u) { if (p < MAXNB) outp[p] = (unsigned char)(e0 + 1); p++; }
        if (nib & 4u) { if (p < MAXNB) outp[p] = (unsigned char)(e0 + 2); p++; }
        if (nib & 8u) { if (p < MAXNB) outp[p] = (unsigned char)(e0 + 3); p++; }
        if (lane == 31) outp[31] = (unsigned char)(incl > MAXNB ? MAXNB : incl);
    }
}

// ---------------------------------------------------------------------------
// Kernel 1: Wh = X @ W (fp32), fused s1/s2; stores TRANSPOSED fp16 WhT[b][o][n].
// W in smem (128 KB); warp computes 4 rows; lane owns 4 features; CTA-local
// smem transpose before coalesced 16 B stores.
// ---------------------------------------------------------------------------
__global__ void __launch_bounds__(256) gat_wh_kernel(
    const float* __restrict__ X,
    const float* __restrict__ W,
    const float* __restrict__ a_vec)
{
    extern __shared__ float smem[];
    float* Wsm = smem;                 // 32768 floats (128 KB)
    float* Xs  = smem + FIN * FOUT;    // 8192 floats (32 KB); reused for T

    const int tid  = threadIdx.x;
    const int warp = tid >> 5;
    const int lane = tid & 31;

    {
        const float4* W4   = reinterpret_cast<const float4*>(W);
        float4*       Wsm4 = reinterpret_cast<float4*>(Wsm);
        #pragma unroll
        for (int i = 0; i < (FIN * FOUT / 4) / 256; i++)
            Wsm4[tid + i * 256] = W4[tid + i * 256];
    }
    __syncthreads();

    const int row0 = (blockIdx.x * 8 + warp) * 4;

    float* Xw = Xs + warp * (4 * FIN);
    {
        const float4* Xg  = reinterpret_cast<const float4*>(X + (size_t)row0 * FIN);
        float4*       Xw4 = reinterpret_cast<float4*>(Xw);
        #pragma unroll
        for (int i = 0; i < (4 * FIN / 4) / 32; i++)
            Xw4[lane + i * 32] = Xg[lane + i * 32];
    }
    __syncwarp();

    float acc[4][4];
    #pragma unroll
    for (int r = 0; r < 4; r++)
        #pragma unroll
        for (int j = 0; j < 4; j++) acc[r][j] = 0.0f;

    #pragma unroll 4
    for (int k = 0; k < FIN; k++) {
        float4 wv = reinterpret_cast<const float4*>(Wsm + k * FOUT)[lane];
        float xv[4];
        #pragma unroll
        for (int r = 0; r < 4; r++) xv[r] = Xw[r * FIN + k];
        #pragma unroll
        for (int r = 0; r < 4; r++) {
            acc[r][0] += xv[r] * wv.x;
            acc[r][1] += xv[r] * wv.y;
            acc[r][2] += xv[r] * wv.z;
            acc[r][3] += xv[r] * wv.w;
        }
    }

    float a1v[4], a2v[4];
    #pragma unroll
    for (int j = 0; j < 4; j++) {
        a1v[j] = __ldg(&a_vec[lane * 4 + j]);
        a2v[j] = __ldg(&a_vec[FOUT + lane * 4 + j]);
    }

    #pragma unroll
    for (int r = 0; r < 4; r++) {
        const int row = row0 + r;
        float p1 = acc[r][0]*a1v[0] + acc[r][1]*a1v[1] + acc[r][2]*a1v[2] + acc[r][3]*a1v[3];
        float p2 = acc[r][0]*a2v[0] + acc[r][1]*a2v[1] + acc[r][2]*a2v[2] + acc[r][3]*a2v[3];
        #pragma unroll
        for (int off = 16; off; off >>= 1) {
            p1 += __shfl_xor_sync(0xffffffffu, p1, off);
            p2 += __shfl_xor_sync(0xffffffffu, p2, off);
        }
        if (lane == 0) { g_s1[row] = p1; g_s2[row] = p2; }
    }

    // ---- transpose to WhT[b][o][n] via smem (pitch 40 halves = 80 B) ----
    __syncthreads();                       // everyone done reading Xs
    __half* T = reinterpret_cast<__half*>(Xs);
    #pragma unroll
    for (int r = 0; r < 4; r++)
        #pragma unroll
        for (int j = 0; j < 4; j++)
            T[(lane * 4 + j) * 40 + warp * 4 + r] = __float2half(acc[r][j]);
    __syncthreads();

    const int gb = (blockIdx.x * 32) >> 11;      // batch
    const int n0 = (blockIdx.x * 32) & 2047;     // n offset within batch
    __half* dstb = g_WhT + (size_t)gb * FOUT * NN + n0;
    #pragma unroll
    for (int i = 0; i < 2; i++) {
        int id = tid + i * 256;                  // 512 chunks of 16 B
        int o = id >> 2, q = id & 3;
        const uint4 v = *reinterpret_cast<const uint4*>(
            reinterpret_cast<const char*>(T) + o * 80 + q * 16);
        *reinterpret_cast<uint4*>(
            reinterpret_cast<char*>(dstb + (size_t)o * NN) + q * 16) = v;
    }
}

// ---------------------------------------------------------------------------
// Kernel 2: WMMA masked-softmax aggregation.  CTA = 128 m-rows, 512 threads.
// Per n-tile: zero+scatter fp16 weights into padded P tile [128][136],
// Wh tile [o=128][n=136] double-buffered via cp.async, then 16 warps in a
// 4x4 (m,o) grid run wmma 16x16x16 (A=P row-major, B=WhT col-major),
// fp32 accumulators resident in registers across all 16 tiles.
// ---------------------------------------------------------------------------
#define LDP 136
#define LDW 136
#define SM_P    0
#define SM_W0   34816
#define SM_W1   69632
#define SM_S2   104448
#define SM_WSUM 112640
#define SM_ATTN_TOTAL 113152

__global__ void __launch_bounds__(512) gat_attn_kernel(float* __restrict__ out)
{
    extern __shared__ char smemc[];
    const uint32_t su = (uint32_t)__cvta_generic_to_shared(smemc);
    __half* Pt   = reinterpret_cast<__half*>(smemc + SM_P);
    float*  s2s  = reinterpret_cast<float*>(smemc + SM_S2);
    float*  wsum_s = reinterpret_cast<float*>(smemc + SM_WSUM);

    const int tid  = threadIdx.x;
    const int warp = tid >> 5;
    const int lane = tid & 31;

    const int blk   = blockIdx.x;          // 128 CTAs: 8 batches x 16 m-tiles
    const int b     = blk >> 4;
    const int rowg0 = blk * 128;
    const int myr0  = warp * 8;            // scatter: this warp's 8 rows

    // stage s2 row (2048 floats)
    {
        const float4* s = reinterpret_cast<const float4*>(g_s2 + (size_t)b * NN);
        reinterpret_cast<float4*>(s2s)[tid] = s[tid];
    }

    float s1r[8], wsumL[8];
    #pragma unroll
    for (int r = 0; r < 8; r++) { s1r[r] = g_s1[rowg0 + myr0 + r]; wsumL[r] = 0.f; }

    const __half* WhTb = g_WhT + (size_t)b * FOUT * NN;

    // Prologue: stage Wh tile 0 into W0
    #pragma unroll
    for (int i = 0; i < 4; i++) {
        int id = tid + i * 512; int o = id >> 4, c = id & 15;
        cpa16(su + SM_W0 + (uint32_t)(o * LDW * 2 + c * 16), WhTb + (size_t)o * NN + c * 8);
    }
    CP_COMMIT();

    unsigned recs[8], nrecs[8];
    #pragma unroll
    for (int r = 0; r < 8; r++)
        recs[r] = g_rec[((size_t)(rowg0 + myr0 + r) * TILES) * 32 + lane];

    // WMMA setup: warp (mw, ow) computes out block [mw*32..+32) x [ow*32..+32)
    const int mw = warp & 3, ow = warp >> 2;
    wmma::fragment<wmma::accumulator, 16, 16, 16, float> cf[2][2];
    #pragma unroll
    for (int i = 0; i < 2; i++)
        #pragma unroll
        for (int j = 0; j < 2; j++) wmma::fill_fragment(cf[i][j], 0.0f);

    for (int t = 0; t < TILES; t++) {
        __syncthreads();    // prev tile's MMA reads of P done; buffers reusable

        // zero P tile (128 x 136 halves = 34816 B = 2176 uint4)
        {
            uint4* pz = reinterpret_cast<uint4*>(Pt);
            uint4 z = make_uint4(0, 0, 0, 0);
            #pragma unroll
            for (int i = 0; i < 4; i++) pz[tid + i * 512] = z;
            if (tid < 128) pz[tid + 2048] = z;
        }
        __syncthreads();

        // scatter weights into P; accumulate wsum from the rounded fp16 values
        #pragma unroll
        for (int r = 0; r < 8; r++) {
            unsigned rec = recs[r];
            int cnt = __shfl_sync(0xffffffffu, (int)rec, 31);
            if (cnt == 0) continue;
            if (lane < cnt) {
                int ri = (int)(rec & 127u);
                float e = s1r[r] + s2s[t * NT + ri];
                e = fmaxf(e, ALPHA * e);                 // leaky relu
                __half h = __float2half(__expf(e));
                wsumL[r] += __half2float(h);
                Pt[(myr0 + r) * LDP + ri] = h;
            }
        }
        // prefetch next tile's records
        if (t + 1 < TILES) {
            #pragma unroll
            for (int r = 0; r < 8; r++)
                nrecs[r] = g_rec[((size_t)(rowg0 + myr0 + r) * TILES + t + 1) * 32 + lane];
        }

        // stage Wh(t+1); ensure Wh(t) has landed
        if (t + 1 < TILES) {
            const uint32_t wb = su + (((t + 1) & 1) ? SM_W1 : SM_W0);
            #pragma unroll
            for (int i = 0; i < 4; i++) {
                int id = tid + i * 512; int o = id >> 4, c = id & 15;
                cpa16(wb + (uint32_t)(o * LDW * 2 + c * 16),
                      WhTb + (size_t)o * NN + (t + 1) * NT + c * 8);
            }
            CP_COMMIT();
            CP_WAIT1();
        } else {
            CP_WAIT0();
        }
        __syncthreads();     // P scatter + Wh(t) visible to all warps

        // MMA: C += P[m][k] * WhT[o][k]  (A row-major, B col-major over k)
        const __half* Wt = reinterpret_cast<const __half*>(
            smemc + ((t & 1) ? SM_W1 : SM_W0));
        #pragma unroll
        for (int k = 0; k < 8; k++) {
            wmma::fragment<wmma::matrix_a, 16, 16, 16, __half, wmma::row_major> af[2];
            wmma::fragment<wmma::matrix_b, 16, 16, 16, __half, wmma::col_major> bf[2];
            #pragma unroll
            for (int i = 0; i < 2; i++)
                wmma::load_matrix_sync(af[i], Pt + (mw * 32 + i * 16) * LDP + k * 16, LDP);
            #pragma unroll
            for (int j = 0; j < 2; j++)
                wmma::load_matrix_sync(bf[j], Wt + k * 16 + (ow * 32 + j * 16) * LDW, LDW);
            #pragma unroll
            for (int i = 0; i < 2; i++)
                #pragma unroll
                for (int j = 0; j < 2; j++)
                    wmma::mma_sync(cf[i][j], af[i], bf[j], cf[i][j]);
        }
        #pragma unroll
        for (int r = 0; r < 8; r++) recs[r] = nrecs[r];
    }

    // wsum -> smem
    #pragma unroll
    for (int r = 0; r < 8; r++) {
        float v = wsumL[r];
        #pragma unroll
        for (int off = 16; off; off >>= 1) v += __shfl_xor_sync(0xffffffffu, v, off);
        if (lane == 0) wsum_s[myr0 + r] = v;
    }
    __syncthreads();

    // Epilogue: per-warp C staging (32 x 36 f32 = 4608 B each, reuse P/W region)
    float* Cs = reinterpret_cast<float*>(smemc) + warp * (32 * 36);
    #pragma unroll
    for (int i = 0; i < 2; i++)
        #pragma unroll
        for (int j = 0; j < 2; j++)
            wmma::store_matrix_sync(Cs + i * 16 * 36 + j * 16, cf[i][j], 36,
                                    wmma::mem_row_major);
    float invv = 1.0f / wsum_s[mw * 32 + lane];
    __syncwarp();
    float* outB = out + (size_t)rowg0 * FOUT + ow * 32;
    #pragma unroll
    for (int r = 0; r < 32; r++) {
        float iv = __shfl_sync(0xffffffffu, invv, r);
        outB[(size_t)(mw * 32 + r) * FOUT + lane] = Cs[r * 36 + lane] * iv;
    }
}

// ---------------------------------------------------------------------------
extern "C" void kernel_launch(void* const* d_in, const int* in_sizes, int n_in,
                              void* d_out, int out_size)
{
    const float* X = (const float*)d_in[0];
    const float* A = (const float*)d_in[1];
    const float* W = (const float*)d_in[2];
    const float* a = (const float*)d_in[3];
    float* out = (float*)d_out;

    const size_t smemWh = (size_t)(FIN * FOUT + 8 * 4 * FIN) * sizeof(float);  // 160 KB

    cudaFuncSetAttribute(gat_wh_kernel,
                         cudaFuncAttributeMaxDynamicSharedMemorySize, (int)smemWh);
    cudaFuncSetAttribute(gat_attn_kernel,
                         cudaFuncAttributeMaxDynamicSharedMemorySize, SM_ATTN_TOTAL);

    gat_compress_kernel<<<2048, 256>>>(A);
    gat_wh_kernel<<<ROWS_TOTAL / 32, 256, smemWh>>>(X, W, a);
    gat_attn_kernel<<<ROWS_TOTAL / 128, 512, SM_ATTN_TOTAL>>>(out);
}